// round 1
// baseline (speedup 1.0000x reference)
#include <cuda_runtime.h>

// FlashAttention: B=2, H=16, HKV=4 (GQA G=4), S=2048, D=128,
// causal + sliding window W=512, fp32 in/out.
// Round 0: fp32 SIMT tiled flash attention (baseline for tensor-core rounds).

#define BM   64
#define BN   64
#define HD   128
#define SEQ  2048
#define WIN  512
#define NBATCH 2
#define NHEAD  16
#define NKV    4
#define GQ     (NHEAD / NKV)
#define PSS    68          // padded P row stride (floats)
#define NTHREADS 256

#define SMEM_FLOATS (HD*BM + HD*BN + BN*HD + BM*PSS)
#define SMEM_BYTES  (SMEM_FLOATS * 4)

__global__ __launch_bounds__(NTHREADS, 1)
void fa_fp32_kernel(const float* __restrict__ Q, const float* __restrict__ K,
                    const float* __restrict__ V, float* __restrict__ O)
{
    extern __shared__ float smem[];
    float* Qs = smem;              // [HD][BM]  (transposed: d-major)
    float* Ks = Qs + HD * BM;      // [HD][BN]  (transposed)
    float* Vs = Ks + HD * BN;      // [BN][HD]  (row-major)
    float* Ps = Vs + BN * HD;      // [BM][PSS] (padded)

    const int m0 = blockIdx.x * BM;
    const int h  = blockIdx.y;
    const int b  = blockIdx.z;
    const int hk = h / GQ;

    const int tid = threadIdx.x;
    const int ty  = tid >> 4;      // 0..15 (row group)
    const int tx  = tid & 15;      // 0..15 (col group)

    const float scale = 0.08838834764831845f;  // 1/sqrt(128)

    const float* qbase = Q + (((size_t)b * NHEAD + h)  * SEQ + m0) * HD;
    const float* kbase = K + (((size_t)b * NKV   + hk) * SEQ)      * HD;
    const float* vbase = V + (((size_t)b * NKV   + hk) * SEQ)      * HD;
    float*       obase = O + (((size_t)b * NHEAD + h)  * SEQ + m0) * HD;

    // ---- load Q tile, transposed + pre-scaled: Qs[d][m] ----
    {
        const int row = tid & 63;
        const int dv0 = tid >> 6;                 // 0..3
#pragma unroll
        for (int it = 0; it < 8; ++it) {
            const int dv = it * 4 + dv0;          // 0..31
            const float4 t4 = *(const float4*)(qbase + row * HD + dv * 4);
            Qs[(dv * 4 + 0) * BM + row] = t4.x * scale;
            Qs[(dv * 4 + 1) * BM + row] = t4.y * scale;
            Qs[(dv * 4 + 2) * BM + row] = t4.z * scale;
            Qs[(dv * 4 + 3) * BM + row] = t4.w * scale;
        }
    }

    float o[4][8];
#pragma unroll
    for (int i = 0; i < 4; ++i)
#pragma unroll
        for (int j = 0; j < 8; ++j) o[i][j] = 0.f;

    float mr[4] = {-1e30f, -1e30f, -1e30f, -1e30f};
    float lr[4] = {0.f, 0.f, 0.f, 0.f};

    const int first_j = m0 - WIN + 1;
    const int t0 = (first_j > 0 ? first_j : 0) / BN;
    const int t1 = m0 / BN;

    for (int nt = t0; nt <= t1; ++nt) {
        const int n0 = nt * BN;
        __syncthreads();   // protect Ks/Vs from previous iteration's PV reads

        // ---- load K tile (transposed) and V tile (row-major) ----
        {
            const int row = tid & 63;
            const int dv0 = tid >> 6;
#pragma unroll
            for (int it = 0; it < 8; ++it) {
                const int dv = it * 4 + dv0;
                const float4 t4 = *(const float4*)(kbase + (size_t)(n0 + row) * HD + dv * 4);
                Ks[(dv * 4 + 0) * BN + row] = t4.x;
                Ks[(dv * 4 + 1) * BN + row] = t4.y;
                Ks[(dv * 4 + 2) * BN + row] = t4.z;
                Ks[(dv * 4 + 3) * BN + row] = t4.w;
            }
            const int vr0 = tid >> 5;             // 0..7
            const int dc  = tid & 31;             // 0..31
#pragma unroll
            for (int it = 0; it < 8; ++it) {
                const int r = it * 8 + vr0;
                *(float4*)(Vs + r * HD + dc * 4) =
                    *(const float4*)(vbase + (size_t)(n0 + r) * HD + dc * 4);
            }
        }
        __syncthreads();

        // ---- S = Q K^T (each thread: 4x4 block) ----
        float s[4][4];
#pragma unroll
        for (int i = 0; i < 4; ++i)
#pragma unroll
            for (int j = 0; j < 4; ++j) s[i][j] = 0.f;

#pragma unroll 8
        for (int d = 0; d < HD; ++d) {
            const float4 a  = *(const float4*)(Qs + d * BM + ty * 4);
            const float4 bb = *(const float4*)(Ks + d * BN + tx * 4);
            s[0][0] += a.x * bb.x; s[0][1] += a.x * bb.y; s[0][2] += a.x * bb.z; s[0][3] += a.x * bb.w;
            s[1][0] += a.y * bb.x; s[1][1] += a.y * bb.y; s[1][2] += a.y * bb.z; s[1][3] += a.y * bb.w;
            s[2][0] += a.z * bb.x; s[2][1] += a.z * bb.y; s[2][2] += a.z * bb.z; s[2][3] += a.z * bb.w;
            s[3][0] += a.w * bb.x; s[3][1] += a.w * bb.y; s[3][2] += a.w * bb.z; s[3][3] += a.w * bb.w;
        }

        // ---- mask (only boundary tiles can have masked elements) ----
        if (nt == t0 || nt == t1) {
#pragma unroll
            for (int i = 0; i < 4; ++i) {
                const int gi = m0 + ty * 4 + i;
#pragma unroll
                for (int j = 0; j < 4; ++j) {
                    const int gj = n0 + tx * 4 + j;
                    if (gj > gi || gi - gj >= WIN) s[i][j] = -2e30f;
                }
            }
        }

        // ---- online softmax (rows shared by the 16 tx lanes of each ty) ----
#pragma unroll
        for (int i = 0; i < 4; ++i) {
            float t = fmaxf(fmaxf(s[i][0], s[i][1]), fmaxf(s[i][2], s[i][3]));
            t = fmaxf(t, __shfl_xor_sync(0xffffffffu, t, 1));
            t = fmaxf(t, __shfl_xor_sync(0xffffffffu, t, 2));
            t = fmaxf(t, __shfl_xor_sync(0xffffffffu, t, 4));
            t = fmaxf(t, __shfl_xor_sync(0xffffffffu, t, 8));
            const float mn = fmaxf(mr[i], t);
            const float al = __expf(mr[i] - mn);
            mr[i] = mn;
            const float p0 = __expf(s[i][0] - mn);
            const float p1 = __expf(s[i][1] - mn);
            const float p2 = __expf(s[i][2] - mn);
            const float p3 = __expf(s[i][3] - mn);
            float ts = (p0 + p1) + (p2 + p3);
            ts += __shfl_xor_sync(0xffffffffu, ts, 1);
            ts += __shfl_xor_sync(0xffffffffu, ts, 2);
            ts += __shfl_xor_sync(0xffffffffu, ts, 4);
            ts += __shfl_xor_sync(0xffffffffu, ts, 8);
            lr[i] = lr[i] * al + ts;
#pragma unroll
            for (int dd = 0; dd < 8; ++dd) o[i][dd] *= al;
            *(float4*)(Ps + (ty * 4 + i) * PSS + tx * 4) = make_float4(p0, p1, p2, p3);
        }
        __syncthreads();

        // ---- O += P V  (thread owns rows ty*4.., cols d=tx*4.. and 64+tx*4..) ----
#pragma unroll 4
        for (int n = 0; n < BN; ++n) {
            const float a0 = Ps[(ty * 4 + 0) * PSS + n];
            const float a1 = Ps[(ty * 4 + 1) * PSS + n];
            const float a2 = Ps[(ty * 4 + 2) * PSS + n];
            const float a3 = Ps[(ty * 4 + 3) * PSS + n];
            const float4 b0 = *(const float4*)(Vs + n * HD + tx * 4);
            const float4 b1 = *(const float4*)(Vs + n * HD + 64 + tx * 4);
            o[0][0] += a0 * b0.x; o[0][1] += a0 * b0.y; o[0][2] += a0 * b0.z; o[0][3] += a0 * b0.w;
            o[0][4] += a0 * b1.x; o[0][5] += a0 * b1.y; o[0][6] += a0 * b1.z; o[0][7] += a0 * b1.w;
            o[1][0] += a1 * b0.x; o[1][1] += a1 * b0.y; o[1][2] += a1 * b0.z; o[1][3] += a1 * b0.w;
            o[1][4] += a1 * b1.x; o[1][5] += a1 * b1.y; o[1][6] += a1 * b1.z; o[1][7] += a1 * b1.w;
            o[2][0] += a2 * b0.x; o[2][1] += a2 * b0.y; o[2][2] += a2 * b0.z; o[2][3] += a2 * b0.w;
            o[2][4] += a2 * b1.x; o[2][5] += a2 * b1.y; o[2][6] += a2 * b1.z; o[2][7] += a2 * b1.w;
            o[3][0] += a3 * b0.x; o[3][1] += a3 * b0.y; o[3][2] += a3 * b0.z; o[3][3] += a3 * b0.w;
            o[3][4] += a3 * b1.x; o[3][5] += a3 * b1.y; o[3][6] += a3 * b1.z; o[3][7] += a3 * b1.w;
        }
    }

    // ---- epilogue: normalize and store ----
#pragma unroll
    for (int i = 0; i < 4; ++i) {
        const float inv = 1.0f / lr[i];
        float4 r0, r1;
        r0.x = o[i][0] * inv; r0.y = o[i][1] * inv; r0.z = o[i][2] * inv; r0.w = o[i][3] * inv;
        r1.x = o[i][4] * inv; r1.y = o[i][5] * inv; r1.z = o[i][6] * inv; r1.w = o[i][7] * inv;
        *(float4*)(obase + (ty * 4 + i) * HD + tx * 4)      = r0;
        *(float4*)(obase + (ty * 4 + i) * HD + 64 + tx * 4) = r1;
    }
}

extern "C" void kernel_launch(void* const* d_in, const int* in_sizes, int n_in,
                              void* d_out, int out_size) {
    (void)in_sizes; (void)n_in; (void)out_size;
    const float* q = (const float*)d_in[0];
    const float* k = (const float*)d_in[1];
    const float* v = (const float*)d_in[2];
    float* out = (float*)d_out;

    // Idempotent attribute set (not a stream op; safe under graph capture).
    cudaFuncSetAttribute(fa_fp32_kernel,
                         cudaFuncAttributeMaxDynamicSharedMemorySize, SMEM_BYTES);

    dim3 grid(SEQ / BM, NHEAD, NBATCH);
    fa_fp32_kernel<<<grid, NTHREADS, SMEM_BYTES>>>(q, k, v, out);
}